// round 10
// baseline (speedup 1.0000x reference)
#include <cuda_runtime.h>
#include <math.h>
#include <stdint.h>

#define BB 4
#define LL 2048
#define IN_DIM 64
#define DM 256
#define DI 512
#define DS 16
#define DCONV 4
#define DTR 16
#define NLAYERS 4
#define BL (BB*LL)   // 8192 rows
#define DG 8         // d's per scan block

// ---------------- scratch (static __device__, no allocation) ----------------
__device__ float g_h[BL*DM];
__device__ float g_xz[BL*2*DI];
__device__ float g_u[BL*DI];
__device__ float g_dbc[BL*48];
__device__ float g_y[BL*DI];
__device__ float g_ln[BL*DM];

// ---------------- helpers ----------------------------------------------------
__device__ __forceinline__ uint32_t smem_u32(const void* p) {
    uint32_t a;
    asm("{ .reg .u64 t; cvta.to.shared.u64 t, %1; cvt.u32.u64 %0, t; }"
        : "=r"(a) : "l"(p));
    return a;
}
__device__ __forceinline__ uint32_t f2tf32(float x) {
    uint32_t u;
    asm("cvt.rna.tf32.f32 %0, %1;" : "=r"(u) : "f"(x));
    return u;
}
__device__ __forceinline__ void mma16n8k8(float* d, const uint32_t* a, const uint32_t* b) {
    asm volatile(
        "mma.sync.aligned.m16n8k8.row.col.f32.tf32.tf32.f32 "
        "{%0,%1,%2,%3}, {%4,%5,%6,%7}, {%8,%9}, {%0,%1,%2,%3};"
        : "+f"(d[0]), "+f"(d[1]), "+f"(d[2]), "+f"(d[3])
        : "r"(a[0]), "r"(a[1]), "r"(a[2]), "r"(a[3]), "r"(b[0]), "r"(b[1]));
}
__device__ __forceinline__ void cp16(uint32_t dst, const float* src, int srcsize) {
    asm volatile("cp.async.ca.shared.global [%0], [%1], 16, %2;"
                 :: "r"(dst), "l"(src), "r"(srcsize) : "memory");
}
#define CP_COMMIT()  asm volatile("cp.async.commit_group;" ::: "memory")
#define CP_WAIT(n)   asm volatile("cp.async.wait_group %0;" :: "n"(n) : "memory")

// ================== split-tf32 tensor-core GEMM: C = A @ W^T =================
#define TSTR 20

template<int BMT, int NT>
__global__ __launch_bounds__(NT) void mma_gemm_t(
    const float* __restrict__ A, int lda,
    const float* __restrict__ W,
    const float* __restrict__ bias,
    const float* __restrict__ res,
    float* __restrict__ C,
    int N, int K, int act)
{
    constexpr int APT = BMT * 4 / NT;
    constexpr int BPT = 64 * 4 / NT;

    __shared__ float sA[2][BMT*TSTR];
    __shared__ float sB[2][64*TSTR];

    int tid = threadIdx.x;
    int wid = tid >> 5, lid = tid & 31;
    int warp_m = wid >> 1;
    int warp_n = wid & 1;
    int bm = blockIdx.y * BMT;
    int bn = blockIdx.x * 64;

    uint32_t aBase = smem_u32(&sA[0][0]);
    uint32_t bBase = smem_u32(&sB[0][0]);
    const uint32_t A_STAGE = BMT*TSTR*4;
    const uint32_t B_STAGE = 64*TSTR*4;

    int arr[APT], ac4[APT];
    #pragma unroll
    for (int j = 0; j < APT; j++) {
        int e = tid + j*NT;
        arr[j] = e >> 2; ac4[j] = (e & 3) * 4;
    }
    int brr[BPT], bc4[BPT], bpred[BPT];
    const float* bsrc[BPT];
    #pragma unroll
    for (int j = 0; j < BPT; j++) {
        int e = tid + j*NT;
        brr[j] = e >> 2; bc4[j] = (e & 3) * 4;
        int gn = bn + brr[j];
        bpred[j] = (gn < N) ? 16 : 0;
        bsrc[j] = W + (size_t)((gn < N) ? gn : 0) * K;
    }

    float acc[2][4][4];
    #pragma unroll
    for (int i = 0; i < 2; i++)
        #pragma unroll
        for (int j = 0; j < 4; j++)
            #pragma unroll
            for (int e = 0; e < 4; e++) acc[i][j][e] = 0.f;

    int nk = K >> 4;

    #pragma unroll
    for (int j = 0; j < APT; j++)
        cp16(aBase + (uint32_t)((arr[j]*TSTR + ac4[j])*4),
             A + (size_t)(bm + arr[j])*lda + ac4[j], 16);
    #pragma unroll
    for (int j = 0; j < BPT; j++)
        cp16(bBase + (uint32_t)((brr[j]*TSTR + bc4[j])*4), bsrc[j] + bc4[j], bpred[j]);
    CP_COMMIT();

    for (int kc = 0; kc < nk; kc++) {
        int cur = kc & 1;
        if (kc + 1 < nk) {
            int k0 = (kc + 1) << 4;
            uint32_t so = (uint32_t)((kc + 1) & 1);
            #pragma unroll
            for (int j = 0; j < APT; j++)
                cp16(aBase + so*A_STAGE + (uint32_t)((arr[j]*TSTR + ac4[j])*4),
                     A + (size_t)(bm + arr[j])*lda + k0 + ac4[j], 16);
            #pragma unroll
            for (int j = 0; j < BPT; j++)
                cp16(bBase + so*B_STAGE + (uint32_t)((brr[j]*TSTR + bc4[j])*4),
                     bsrc[j] + k0 + bc4[j], bpred[j]);
            CP_COMMIT();
            CP_WAIT(1);
        } else {
            CP_WAIT(0);
        }
        __syncthreads();

        const float* cA = sA[cur];
        const float* cB = sB[cur];

        #pragma unroll
        for (int ks = 0; ks < 2; ks++) {
            int kk = ks * 8;
            uint32_t ah[2][4], al[2][4];
            {
                int r0 = warp_m*32 + (lid >> 2);
                int c0 = kk + (lid & 3);
                #pragma unroll
                for (int im = 0; im < 2; im++) {
                    const float* pa = cA + (r0 + im*16)*TSTR + c0;
                    float f0 = pa[0], f1 = pa[8*TSTR], f2 = pa[4], f3 = pa[8*TSTR + 4];
                    ah[im][0] = f2tf32(f0); al[im][0] = f2tf32(f0 - __uint_as_float(ah[im][0]));
                    ah[im][1] = f2tf32(f1); al[im][1] = f2tf32(f1 - __uint_as_float(ah[im][1]));
                    ah[im][2] = f2tf32(f2); al[im][2] = f2tf32(f2 - __uint_as_float(ah[im][2]));
                    ah[im][3] = f2tf32(f3); al[im][3] = f2tf32(f3 - __uint_as_float(ah[im][3]));
                }
            }
            uint32_t bh[4][2], bl[4][2];
            {
                int n0 = warp_n*32 + (lid >> 2);
                int c0 = kk + (lid & 3);
                #pragma unroll
                for (int jn = 0; jn < 4; jn++) {
                    const float* pb = cB + (n0 + jn*8)*TSTR + c0;
                    float f0 = pb[0], f1 = pb[4];
                    bh[jn][0] = f2tf32(f0); bl[jn][0] = f2tf32(f0 - __uint_as_float(bh[jn][0]));
                    bh[jn][1] = f2tf32(f1); bl[jn][1] = f2tf32(f1 - __uint_as_float(bh[jn][1]));
                }
            }
            #pragma unroll
            for (int im = 0; im < 2; im++)
                #pragma unroll
                for (int jn = 0; jn < 4; jn++) {
                    mma16n8k8(acc[im][jn], ah[im], bh[jn]);
                    mma16n8k8(acc[im][jn], al[im], bh[jn]);
                    mma16n8k8(acc[im][jn], ah[im], bl[jn]);
                }
        }
        __syncthreads();
    }

    int gm0 = bm + warp_m*32 + (lid >> 2);
    int gnb = bn + warp_n*32 + 2*(lid & 3);
    #pragma unroll
    for (int im = 0; im < 2; im++) {
        #pragma unroll
        for (int jn = 0; jn < 4; jn++) {
            int gn = gnb + jn*8;
            if (gn < N) {
                float b0 = 0.f, b1 = 0.f;
                if (bias) { b0 = bias[gn]; b1 = bias[gn+1]; }
                #pragma unroll
                for (int half = 0; half < 2; half++) {
                    int gm = gm0 + im*16 + half*8;
                    float v0 = acc[im][jn][half*2+0] + b0;
                    float v1 = acc[im][jn][half*2+1] + b1;
                    if (act == 1) {
                        v0 = (v0 > 15.f) ? v0 : log1pf(__expf(v0));
                        v1 = (v1 > 15.f) ? v1 : log1pf(__expf(v1));
                    }
                    if (res) {
                        float2 rv = *(const float2*)(res + (size_t)gm*N + gn);
                        v0 += rv.x; v1 += rv.y;
                    }
                    *(float2*)(C + (size_t)gm*N + gn) = make_float2(v0, v1);
                }
            }
        }
    }
}

// ---------------- depthwise causal conv (width 4) + SiLU --------------------
__global__ void conv_silu_kernel(const float* __restrict__ xz,
                                 const float* __restrict__ convw,
                                 const float* __restrict__ convb,
                                 float* __restrict__ u)
{
    int idx = blockIdx.x * blockDim.x + threadIdx.x;
    if (idx >= BL*DI) return;
    int d  = idx & (DI-1);
    int bt = idx >> 9;
    int t  = bt & (LL-1);

    float acc = convb[d];
    #pragma unroll
    for (int k = 0; k < DCONV; k++) {
        int tt = t - (DCONV-1) + k;
        if (tt >= 0)
            acc = fmaf(xz[(size_t)(bt - (DCONV-1) + k)*(2*DI) + d],
                       convw[d*DCONV + k], acc);
    }
    float sig = 1.f / (1.f + __expf(-acc));
    u[idx] = acc * sig;
}

// ====== d-grouped chunked scan: block per (b, 8 d's), delta fused ===========
// Dynamic smem: delta[DG][LL] + u[DG][LL] = 128KB. B/C loads reused 8x.
__global__ __launch_bounds__(256) void scan3_kernel(
    const float* __restrict__ xz,
    const float* __restrict__ u_arr,
    const float* __restrict__ dbc,
    const float* __restrict__ dtw,     // [DI, 16] layer slice
    const float* __restrict__ dtb,     // [DI]
    const float* __restrict__ a_log,   // [DI, DS]
    const float* __restrict__ dparam,  // [DI]
    float* __restrict__ y_arr)
{
    extern __shared__ float dyn[];
    float* s_delta = dyn;              // [DG][LL]
    float* s_u     = dyn + DG*LL;      // [DG][LL]
    __shared__ float sC[DG][16][17];
    __shared__ float sP[DG][16][17];
    __shared__ float s_w[DG][DTR];
    __shared__ float s_wb[DG];

    int blk = blockIdx.x;              // 0..255
    int b   = blk >> 6;
    int d0  = (blk & 63) * DG;
    int tid = threadIdx.x;
    int s   = tid & 15, ck = tid >> 4;
    int t0  = ck * 128;
    int base = b * LL;

    if (tid < DG*DTR) s_w[tid >> 4][tid & 15] = dtw[(d0 + (tid >> 4))*DTR + (tid & 15)];
    if (tid < DG)     s_wb[tid] = dtb[d0 + tid];
    __syncthreads();

    // ---- stage A: delta (softplus of dt.dtw + dtb) and u into smem ----
    for (int t = tid; t < LL; t += 256) {
        int row = base + t;
        const float4* p = (const float4*)(dbc + (size_t)row*48);
        float4 q0 = p[0], q1 = p[1], q2 = p[2], q3 = p[3];
        float4 ua = *(const float4*)(u_arr + (size_t)row*DI + d0);
        float4 ub = *(const float4*)(u_arr + (size_t)row*DI + d0 + 4);
        float uu[DG] = {ua.x, ua.y, ua.z, ua.w, ub.x, ub.y, ub.z, ub.w};
        #pragma unroll
        for (int j = 0; j < DG; j++) {
            const float* w = s_w[j];
            float a = q0.x*w[0];
            a = fmaf(q0.y, w[1], a);  a = fmaf(q0.z, w[2], a);  a = fmaf(q0.w, w[3], a);
            a = fmaf(q1.x, w[4], a);  a = fmaf(q1.y, w[5], a);  a = fmaf(q1.z, w[6], a);
            a = fmaf(q1.w, w[7], a);
            a = fmaf(q2.x, w[8], a);  a = fmaf(q2.y, w[9], a);  a = fmaf(q2.z, w[10], a);
            a = fmaf(q2.w, w[11], a);
            a = fmaf(q3.x, w[12], a); a = fmaf(q3.y, w[13], a); a = fmaf(q3.z, w[14], a);
            a = fmaf(q3.w, w[15], a);
            a += s_wb[j];
            s_delta[j*LL + t] = (a > 15.f) ? a : log1pf(__expf(a));
            s_u[j*LL + t] = uu[j];
        }
    }
    __syncthreads();

    float A[DG];
    #pragma unroll
    for (int j = 0; j < DG; j++)
        A[j] = -__expf(a_log[(size_t)(d0 + j)*DS + s]);

    // ---- pass 1: chunk-local scans (B load shared across 8 d's) ----
    float hl[DG], sd[DG];
    #pragma unroll
    for (int j = 0; j < DG; j++) { hl[j] = 0.f; sd[j] = 0.f; }
    for (int i = 0; i < 128; i++) {
        int t = t0 + i;
        float Bt = dbc[(size_t)(base + t)*48 + DTR + s];
        #pragma unroll
        for (int j = 0; j < DG; j++) {
            float de = s_delta[j*LL + t];
            hl[j] = fmaf(__expf(de * A[j]), hl[j], de * s_u[j*LL + t] * Bt);
            sd[j] += de;
        }
    }
    #pragma unroll
    for (int j = 0; j < DG; j++) {
        sC[j][ck][s] = hl[j];
        sP[j][ck][s] = __expf(sd[j] * A[j]);
    }
    __syncthreads();

    // ---- prefix over chunks: 128 threads = (j, s) pairs ----
    if (tid < DG*16) {
        int j = tid >> 4, ss = tid & 15;
        float h = 0.f;
        #pragma unroll
        for (int c = 0; c < 16; c++) {
            float nh = fmaf(sP[j][c][ss], h, sC[j][c][ss]);
            sC[j][c][ss] = h;
            h = nh;
        }
    }
    __syncthreads();

    // ---- pass 2: rescan with true h_start, emit gated y ----
    float h2[DG], Dp[DG];
    #pragma unroll
    for (int j = 0; j < DG; j++) { h2[j] = sC[j][ck][s]; Dp[j] = dparam[d0 + j]; }

    for (int i = 0; i < 128; i++) {
        int t = t0 + i;
        int row = base + t;
        float Bt = dbc[(size_t)row*48 + DTR + s];
        float Ct = dbc[(size_t)row*48 + DTR + DS + s];
        float yv[DG];
        #pragma unroll
        for (int j = 0; j < DG; j++) {
            float de = s_delta[j*LL + t];
            float uu = s_u[j*LL + t];
            h2[j] = fmaf(__expf(de * A[j]), h2[j], de * uu * Bt);
            float p = h2[j] * Ct;
            p += __shfl_xor_sync(0xffffffffu, p, 8);
            p += __shfl_xor_sync(0xffffffffu, p, 4);
            p += __shfl_xor_sync(0xffffffffu, p, 2);
            p += __shfl_xor_sync(0xffffffffu, p, 1);
            yv[j] = fmaf(uu, Dp[j], p);
        }
        if (s == 0) {
            float4 za = *(const float4*)(xz + (size_t)row*(2*DI) + DI + d0);
            float4 zb = *(const float4*)(xz + (size_t)row*(2*DI) + DI + d0 + 4);
            float zz[DG] = {za.x, za.y, za.z, za.w, zb.x, zb.y, zb.z, zb.w};
            float out[DG];
            #pragma unroll
            for (int j = 0; j < DG; j++) {
                float sig = 1.f / (1.f + __expf(-zz[j]));
                out[j] = yv[j] * (zz[j] * sig);
            }
            *(float4*)(y_arr + (size_t)row*DI + d0) =
                make_float4(out[0], out[1], out[2], out[3]);
            *(float4*)(y_arr + (size_t)row*DI + d0 + 4) =
                make_float4(out[4], out[5], out[6], out[7]);
        }
    }
}

// ---------------- layernorm over 256 features (one warp per row) ------------
__global__ void ln_kernel(const float* __restrict__ x,
                          const float* __restrict__ w,
                          const float* __restrict__ b,
                          float* __restrict__ out)
{
    int warp = (blockIdx.x * blockDim.x + threadIdx.x) >> 5;
    int lane = threadIdx.x & 31;
    if (warp >= BL) return;
    const float* row = x + (size_t)warp*DM;

    float v[8];
    float sum = 0.f, sq = 0.f;
    #pragma unroll
    for (int k = 0; k < 8; k++) {
        v[k] = row[lane + k*32];
        sum += v[k];
        sq = fmaf(v[k], v[k], sq);
    }
    #pragma unroll
    for (int o = 16; o; o >>= 1) {
        sum += __shfl_xor_sync(0xffffffffu, sum, o);
        sq  += __shfl_xor_sync(0xffffffffu, sq,  o);
    }
    float mu  = sum * (1.f/DM);
    float var = sq * (1.f/DM) - mu*mu;
    float inv = rsqrtf(var + 1e-5f);
    #pragma unroll
    for (int k = 0; k < 8; k++) {
        int c = lane + k*32;
        out[(size_t)warp*DM + c] = (v[k]-mu)*inv*w[c] + b[c];
    }
}

// ---------------- host orchestration ----------------------------------------
#define SCAN_SMEM (DG*LL*2*4)   // 131072 B

static inline void launch_gemm_big(const float* A, int lda, const float* W,
                                   const float* bias, const float* res,
                                   float* C, int N, int K, int act)
{
    dim3 grid((N + 63) / 64, BL / 128);
    mma_gemm_t<128, 256><<<grid, 256>>>(A, lda, W, bias, res, C, N, K, act);
}
static inline void launch_gemm_small(const float* A, int lda, const float* W,
                                     const float* bias, const float* res,
                                     float* C, int N, int K, int act)
{
    dim3 grid((N + 63) / 64, BL / 64);
    mma_gemm_t<64, 128><<<grid, 128>>>(A, lda, W, bias, res, C, N, K, act);
}

extern "C" void kernel_launch(void* const* d_in, const int* in_sizes, int n_in,
                              void* d_out, int out_size)
{
    const float* x          = (const float*)d_in[0];
    const float* in_proj_w  = (const float*)d_in[1];
    const float* in_proj_b  = (const float*)d_in[2];
    const float* out_proj_w = (const float*)d_in[3];
    const float* out_proj_b = (const float*)d_in[4];
    const float* inw        = (const float*)d_in[5];
    const float* convw      = (const float*)d_in[6];
    const float* convb      = (const float*)d_in[7];
    const float* xpw        = (const float*)d_in[8];
    const float* dtw        = (const float*)d_in[9];
    const float* dtb        = (const float*)d_in[10];
    const float* a_log      = (const float*)d_in[11];
    const float* dparam     = (const float*)d_in[12];
    const float* outw       = (const float*)d_in[13];
    const float* lnw        = (const float*)d_in[14];
    const float* lnb        = (const float*)d_in[15];
    float* out = (float*)d_out;

    cudaFuncSetAttribute(scan3_kernel,
                         cudaFuncAttributeMaxDynamicSharedMemorySize, SCAN_SMEM);

    float *h, *xz, *u, *dbc, *y, *ln;
    cudaGetSymbolAddress((void**)&h,   g_h);
    cudaGetSymbolAddress((void**)&xz,  g_xz);
    cudaGetSymbolAddress((void**)&u,   g_u);
    cudaGetSymbolAddress((void**)&dbc, g_dbc);
    cudaGetSymbolAddress((void**)&y,   g_y);
    cudaGetSymbolAddress((void**)&ln,  g_ln);

    // h = x @ in_proj_w^T + in_proj_b
    launch_gemm_big(x, IN_DIM, in_proj_w, in_proj_b, nullptr, h, DM, IN_DIM, 0);

    for (int l = 0; l < NLAYERS; l++) {
        // xz = h @ inw[l]^T
        launch_gemm_big(h, DM, inw + (size_t)l*2*DI*DM, nullptr, nullptr, xz, 2*DI, DM, 0);
        // u = silu(causal_conv(xz[:, :DI]))
        conv_silu_kernel<<<(BL*DI)/256, 256>>>(xz, convw + l*DI*DCONV, convb + l*DI, u);
        // dbc = u @ xpw[l]^T   (N=48, small tile)
        launch_gemm_small(u, DI, xpw + (size_t)l*48*DI, nullptr, nullptr, dbc, 48, DI, 0);
        // d-grouped chunked scan (delta fused) + gating
        scan3_kernel<<<BB*(DI/DG), 256, SCAN_SMEM>>>(xz, u, dbc,
                                     dtw + (size_t)l*DI*DTR, dtb + l*DI,
                                     a_log + (size_t)l*DI*DS, dparam + l*DI, y);
        // ln_in = y @ outw[l]^T + residual(h)
        launch_gemm_big(y, DI, outw + (size_t)l*DM*DI, nullptr, h, ln, DM, DI, 0);
        // h = layernorm(ln_in)
        ln_kernel<<<BL/8, 256>>>(ln, lnw + l*DM, lnb + l*DM, h);
    }

    // out = h @ out_proj_w^T + out_proj_b
    launch_gemm_big(h, DM, out_proj_w, out_proj_b, nullptr, out, DM, DM, 0);
}

// round 11
// speedup vs baseline: 1.2084x; 1.2084x over previous
#include <cuda_runtime.h>
#include <math.h>
#include <stdint.h>

#define BB 4
#define LL 2048
#define IN_DIM 64
#define DM 256
#define DI 512
#define DS 16
#define DCONV 4
#define DTR 16
#define NLAYERS 4
#define BL (BB*LL)   // 8192 rows

// ---------------- scratch (static __device__, no allocation) ----------------
__device__ float g_h[BL*DM];
__device__ float g_xz[BL*2*DI];
__device__ float g_u[BL*DI];
__device__ float g_dbc[BL*48];
__device__ float g_delta[BL*DI];
__device__ float g_y[BL*DI];
__device__ float g_ln[BL*DM];

// ---------------- helpers ----------------------------------------------------
__device__ __forceinline__ uint32_t smem_u32(const void* p) {
    uint32_t a;
    asm("{ .reg .u64 t; cvta.to.shared.u64 t, %1; cvt.u32.u64 %0, t; }"
        : "=r"(a) : "l"(p));
    return a;
}
__device__ __forceinline__ uint32_t f2tf32(float x) {
    uint32_t u;
    asm("cvt.rna.tf32.f32 %0, %1;" : "=r"(u) : "f"(x));
    return u;
}
__device__ __forceinline__ void mma16n8k8(float* d, const uint32_t* a, const uint32_t* b) {
    asm volatile(
        "mma.sync.aligned.m16n8k8.row.col.f32.tf32.tf32.f32 "
        "{%0,%1,%2,%3}, {%4,%5,%6,%7}, {%8,%9}, {%0,%1,%2,%3};"
        : "+f"(d[0]), "+f"(d[1]), "+f"(d[2]), "+f"(d[3])
        : "r"(a[0]), "r"(a[1]), "r"(a[2]), "r"(a[3]), "r"(b[0]), "r"(b[1]));
}
__device__ __forceinline__ void cp16(uint32_t dst, const float* src, int srcsize) {
    asm volatile("cp.async.ca.shared.global [%0], [%1], 16, %2;"
                 :: "r"(dst), "l"(src), "r"(srcsize) : "memory");
}
#define CP_COMMIT()  asm volatile("cp.async.commit_group;" ::: "memory")
#define CP_WAIT(n)   asm volatile("cp.async.wait_group %0;" :: "n"(n) : "memory")

// ================== split-tf32 tensor-core GEMM: C = A @ W^T =================
// Template on (BMT, NT): BMT x 64 tile, NT threads, warp tile 32x32.
// BK=16, cp.async double-buffered smem (R5-proven structure).
#define TSTR 20   // smem row stride in words (conflict-free)

template<int BMT, int NT>
__global__ __launch_bounds__(NT) void mma_gemm_t(
    const float* __restrict__ A, int lda,
    const float* __restrict__ W,
    const float* __restrict__ bias,
    const float* __restrict__ res,
    float* __restrict__ C,
    int N, int K, int act)
{
    constexpr int APT = BMT * 4 / NT;
    constexpr int BPT = 64 * 4 / NT;

    __shared__ float sA[2][BMT*TSTR];
    __shared__ float sB[2][64*TSTR];

    int tid = threadIdx.x;
    int wid = tid >> 5, lid = tid & 31;
    int warp_m = wid >> 1;
    int warp_n = wid & 1;
    int bm = blockIdx.y * BMT;
    int bn = blockIdx.x * 64;

    uint32_t aBase = smem_u32(&sA[0][0]);
    uint32_t bBase = smem_u32(&sB[0][0]);
    const uint32_t A_STAGE = BMT*TSTR*4;
    const uint32_t B_STAGE = 64*TSTR*4;

    int arr[APT], ac4[APT];
    #pragma unroll
    for (int j = 0; j < APT; j++) {
        int e = tid + j*NT;
        arr[j] = e >> 2; ac4[j] = (e & 3) * 4;
    }
    int brr[BPT], bc4[BPT], bpred[BPT];
    const float* bsrc[BPT];
    #pragma unroll
    for (int j = 0; j < BPT; j++) {
        int e = tid + j*NT;
        brr[j] = e >> 2; bc4[j] = (e & 3) * 4;
        int gn = bn + brr[j];
        bpred[j] = (gn < N) ? 16 : 0;
        bsrc[j] = W + (size_t)((gn < N) ? gn : 0) * K;
    }

    float acc[2][4][4];
    #pragma unroll
    for (int i = 0; i < 2; i++)
        #pragma unroll
        for (int j = 0; j < 4; j++)
            #pragma unroll
            for (int e = 0; e < 4; e++) acc[i][j][e] = 0.f;

    int nk = K >> 4;

    // prefetch stage 0
    #pragma unroll
    for (int j = 0; j < APT; j++)
        cp16(aBase + (uint32_t)((arr[j]*TSTR + ac4[j])*4),
             A + (size_t)(bm + arr[j])*lda + ac4[j], 16);
    #pragma unroll
    for (int j = 0; j < BPT; j++)
        cp16(bBase + (uint32_t)((brr[j]*TSTR + bc4[j])*4), bsrc[j] + bc4[j], bpred[j]);
    CP_COMMIT();

    for (int kc = 0; kc < nk; kc++) {
        int cur = kc & 1;
        if (kc + 1 < nk) {
            int k0 = (kc + 1) << 4;
            uint32_t so = (uint32_t)((kc + 1) & 1);
            #pragma unroll
            for (int j = 0; j < APT; j++)
                cp16(aBase + so*A_STAGE + (uint32_t)((arr[j]*TSTR + ac4[j])*4),
                     A + (size_t)(bm + arr[j])*lda + k0 + ac4[j], 16);
            #pragma unroll
            for (int j = 0; j < BPT; j++)
                cp16(bBase + so*B_STAGE + (uint32_t)((brr[j]*TSTR + bc4[j])*4),
                     bsrc[j] + k0 + bc4[j], bpred[j]);
            CP_COMMIT();
            CP_WAIT(1);
        } else {
            CP_WAIT(0);
        }
        __syncthreads();

        const float* cA = sA[cur];
        const float* cB = sB[cur];

        #pragma unroll
        for (int ks = 0; ks < 2; ks++) {
            int kk = ks * 8;
            uint32_t ah[2][4], al[2][4];
            {
                int r0 = warp_m*32 + (lid >> 2);
                int c0 = kk + (lid & 3);
                #pragma unroll
                for (int im = 0; im < 2; im++) {
                    const float* pa = cA + (r0 + im*16)*TSTR + c0;
                    float f0 = pa[0], f1 = pa[8*TSTR], f2 = pa[4], f3 = pa[8*TSTR + 4];
                    ah[im][0] = f2tf32(f0); al[im][0] = f2tf32(f0 - __uint_as_float(ah[im][0]));
                    ah[im][1] = f2tf32(f1); al[im][1] = f2tf32(f1 - __uint_as_float(ah[im][1]));
                    ah[im][2] = f2tf32(f2); al[im][2] = f2tf32(f2 - __uint_as_float(ah[im][2]));
                    ah[im][3] = f2tf32(f3); al[im][3] = f2tf32(f3 - __uint_as_float(ah[im][3]));
                }
            }
            uint32_t bh[4][2], bl[4][2];
            {
                int n0 = warp_n*32 + (lid >> 2);
                int c0 = kk + (lid & 3);
                #pragma unroll
                for (int jn = 0; jn < 4; jn++) {
                    const float* pb = cB + (n0 + jn*8)*TSTR + c0;
                    float f0 = pb[0], f1 = pb[4];
                    bh[jn][0] = f2tf32(f0); bl[jn][0] = f2tf32(f0 - __uint_as_float(bh[jn][0]));
                    bh[jn][1] = f2tf32(f1); bl[jn][1] = f2tf32(f1 - __uint_as_float(bh[jn][1]));
                }
            }
            #pragma unroll
            for (int im = 0; im < 2; im++)
                #pragma unroll
                for (int jn = 0; jn < 4; jn++) {
                    mma16n8k8(acc[im][jn], ah[im], bh[jn]);
                    mma16n8k8(acc[im][jn], al[im], bh[jn]);
                    mma16n8k8(acc[im][jn], ah[im], bl[jn]);
                }
        }
        __syncthreads();
    }

    // ---- epilogue ----
    int gm0 = bm + warp_m*32 + (lid >> 2);
    int gnb = bn + warp_n*32 + 2*(lid & 3);
    #pragma unroll
    for (int im = 0; im < 2; im++) {
        #pragma unroll
        for (int jn = 0; jn < 4; jn++) {
            int gn = gnb + jn*8;
            if (gn < N) {
                float b0 = 0.f, b1 = 0.f;
                if (bias) { b0 = bias[gn]; b1 = bias[gn+1]; }
                #pragma unroll
                for (int half = 0; half < 2; half++) {
                    int gm = gm0 + im*16 + half*8;
                    float v0 = acc[im][jn][half*2+0] + b0;
                    float v1 = acc[im][jn][half*2+1] + b1;
                    if (act == 1) {
                        v0 = (v0 > 15.f) ? v0 : log1pf(__expf(v0));
                        v1 = (v1 > 15.f) ? v1 : log1pf(__expf(v1));
                    }
                    if (res) {
                        float2 rv = *(const float2*)(res + (size_t)gm*N + gn);
                        v0 += rv.x; v1 += rv.y;
                    }
                    *(float2*)(C + (size_t)gm*N + gn) = make_float2(v0, v1);
                }
            }
        }
    }
}

// ---------------- depthwise causal conv (width 4) + SiLU --------------------
__global__ void conv_silu_kernel(const float* __restrict__ xz,
                                 const float* __restrict__ convw,
                                 const float* __restrict__ convb,
                                 float* __restrict__ u)
{
    int idx = blockIdx.x * blockDim.x + threadIdx.x;
    if (idx >= BL*DI) return;
    int d  = idx & (DI-1);
    int bt = idx >> 9;
    int t  = bt & (LL-1);

    float acc = convb[d];
    #pragma unroll
    for (int k = 0; k < DCONV; k++) {
        int tt = t - (DCONV-1) + k;
        if (tt >= 0)
            acc = fmaf(xz[(size_t)(bt - (DCONV-1) + k)*(2*DI) + d],
                       convw[d*DCONV + k], acc);
    }
    float sig = 1.f / (1.f + __expf(-acc));
    u[idx] = acc * sig;
}

// ============ chunked selective scan: block per (b,d), 16 chunks =============
// (R5-proven structure: reads precomputed delta from global)
__global__ __launch_bounds__(256) void scan2_kernel(
    const float* __restrict__ xz,
    const float* __restrict__ u_arr,
    const float* __restrict__ dbc,
    const float* __restrict__ delta_arr,
    const float* __restrict__ a_log,
    const float* __restrict__ dparam,
    float* __restrict__ y_arr)
{
    __shared__ float s_delta[LL];
    __shared__ float s_u[LL];
    __shared__ float sC[16][17];
    __shared__ float sP[16][17];

    int bd = blockIdx.x;
    int d = bd & (DI-1), b = bd >> 9;
    int tid = threadIdx.x;
    int s = tid & 15, ck = tid >> 4;
    int t0 = ck * 128;
    int base = b * LL;

    float A = -__expf(a_log[d*DS + s]);

    // ---- pass 1: chunk-local scan from h=0 ----
    float hloc = 0.f, sd = 0.f;
    #pragma unroll 4
    for (int i = 0; i < 128; i++) {
        int t = t0 + i;
        int row = base + t;
        float delta = delta_arr[(size_t)row*DI + d];
        float uu    = u_arr[(size_t)row*DI + d];
        float Bt    = dbc[(size_t)row*48 + DTR + s];
        float dA = __expf(delta * A);
        hloc = fmaf(dA, hloc, delta * uu * Bt);
        sd += delta;
        if (s == 0) { s_delta[t] = delta; s_u[t] = uu; }
    }
    sC[ck][s] = hloc;
    sP[ck][s] = __expf(sd * A);
    __syncthreads();

    // ---- prefix over chunks ----
    if (tid < 16) {
        float h = 0.f;
        #pragma unroll
        for (int c = 0; c < 16; c++) {
            float nh = fmaf(sP[c][tid], h, sC[c][tid]);
            sC[c][tid] = h;
            h = nh;
        }
    }
    __syncthreads();

    // ---- pass 2: rescan with true h_start, emit y ----
    float h = sC[ck][s];
    float Dp = dparam[d];
    #pragma unroll 4
    for (int i = 0; i < 128; i++) {
        int t = t0 + i;
        int row = base + t;
        float delta = s_delta[t];
        float uu    = s_u[t];
        float Bt    = dbc[(size_t)row*48 + DTR + s];
        float Ct    = dbc[(size_t)row*48 + DTR + DS + s];
        float dA = __expf(delta * A);
        h = fmaf(dA, h, delta * uu * Bt);

        float p = h * Ct;
        p += __shfl_xor_sync(0xffffffffu, p, 8);
        p += __shfl_xor_sync(0xffffffffu, p, 4);
        p += __shfl_xor_sync(0xffffffffu, p, 2);
        p += __shfl_xor_sync(0xffffffffu, p, 1);

        if (s == 0) {
            float z = xz[(size_t)row*(2*DI) + DI + d];
            float sig = 1.f / (1.f + __expf(-z));
            y_arr[(size_t)row*DI + d] = (p + uu * Dp) * (z * sig);
        }
    }
}

// ---------------- layernorm over 256 features (one warp per row) ------------
__global__ void ln_kernel(const float* __restrict__ x,
                          const float* __restrict__ w,
                          const float* __restrict__ b,
                          float* __restrict__ out)
{
    int warp = (blockIdx.x * blockDim.x + threadIdx.x) >> 5;
    int lane = threadIdx.x & 31;
    if (warp >= BL) return;
    const float* row = x + (size_t)warp*DM;

    float v[8];
    float sum = 0.f, sq = 0.f;
    #pragma unroll
    for (int k = 0; k < 8; k++) {
        v[k] = row[lane + k*32];
        sum += v[k];
        sq = fmaf(v[k], v[k], sq);
    }
    #pragma unroll
    for (int o = 16; o; o >>= 1) {
        sum += __shfl_xor_sync(0xffffffffu, sum, o);
        sq  += __shfl_xor_sync(0xffffffffu, sq,  o);
    }
    float mu  = sum * (1.f/DM);
    float var = sq * (1.f/DM) - mu*mu;
    float inv = rsqrtf(var + 1e-5f);
    #pragma unroll
    for (int k = 0; k < 8; k++) {
        int c = lane + k*32;
        out[(size_t)warp*DM + c] = (v[k]-mu)*inv*w[c] + b[c];
    }
}

// ---------------- host orchestration ----------------------------------------
static inline void launch_gemm_big(const float* A, int lda, const float* W,
                                   const float* bias, const float* res,
                                   float* C, int N, int K, int act)
{
    dim3 grid((N + 63) / 64, BL / 128);
    mma_gemm_t<128, 256><<<grid, 256>>>(A, lda, W, bias, res, C, N, K, act);
}
static inline void launch_gemm_small(const float* A, int lda, const float* W,
                                     const float* bias, const float* res,
                                     float* C, int N, int K, int act)
{
    dim3 grid((N + 63) / 64, BL / 64);
    mma_gemm_t<64, 128><<<grid, 128>>>(A, lda, W, bias, res, C, N, K, act);
}

extern "C" void kernel_launch(void* const* d_in, const int* in_sizes, int n_in,
                              void* d_out, int out_size)
{
    const float* x          = (const float*)d_in[0];
    const float* in_proj_w  = (const float*)d_in[1];
    const float* in_proj_b  = (const float*)d_in[2];
    const float* out_proj_w = (const float*)d_in[3];
    const float* out_proj_b = (const float*)d_in[4];
    const float* inw        = (const float*)d_in[5];
    const float* convw      = (const float*)d_in[6];
    const float* convb      = (const float*)d_in[7];
    const float* xpw        = (const float*)d_in[8];
    const float* dtw        = (const float*)d_in[9];
    const float* dtb        = (const float*)d_in[10];
    const float* a_log      = (const float*)d_in[11];
    const float* dparam     = (const float*)d_in[12];
    const float* outw       = (const float*)d_in[13];
    const float* lnw        = (const float*)d_in[14];
    const float* lnb        = (const float*)d_in[15];
    float* out = (float*)d_out;

    float *h, *xz, *u, *dbc, *delta, *y, *ln;
    cudaGetSymbolAddress((void**)&h,     g_h);
    cudaGetSymbolAddress((void**)&xz,    g_xz);
    cudaGetSymbolAddress((void**)&u,     g_u);
    cudaGetSymbolAddress((void**)&dbc,   g_dbc);
    cudaGetSymbolAddress((void**)&delta, g_delta);
    cudaGetSymbolAddress((void**)&y,     g_y);
    cudaGetSymbolAddress((void**)&ln,    g_ln);

    // h = x @ in_proj_w^T + in_proj_b
    launch_gemm_big(x, IN_DIM, in_proj_w, in_proj_b, nullptr, h, DM, IN_DIM, 0);

    for (int l = 0; l < NLAYERS; l++) {
        // xz = h @ inw[l]^T
        launch_gemm_big(h, DM, inw + (size_t)l*2*DI*DM, nullptr, nullptr, xz, 2*DI, DM, 0);
        // u = silu(causal_conv(xz[:, :DI]))
        conv_silu_kernel<<<(BL*DI)/256, 256>>>(xz, convw + l*DI*DCONV, convb + l*DI, u);
        // dbc = u @ xpw[l]^T   (N=48, small tile -> 128 blocks; verified faster)
        launch_gemm_small(u, DI, xpw + (size_t)l*48*DI, nullptr, nullptr, dbc, 48, DI, 0);
        // delta = softplus(dt @ dtw[l]^T + dtb[l])
        launch_gemm_big(dbc, 48, dtw + (size_t)l*DI*DTR, dtb + l*DI, nullptr, delta, DI, DTR, 1);
        // chunked selective scan + gating
        scan2_kernel<<<BB*DI, 256>>>(xz, u, dbc, delta,
                                     a_log + (size_t)l*DI*DS, dparam + l*DI, y);
        // ln_in = y @ outw[l]^T + residual(h)
        launch_gemm_big(y, DI, outw + (size_t)l*DM*DI, nullptr, h, ln, DM, DI, 0);
        // h = layernorm(ln_in)
        ln_kernel<<<BL/8, 256>>>(ln, lnw + l*DM, lnb + l*DM, h);
    }

    // out = h @ out_proj_w^T + out_proj_b
    launch_gemm_big(h, DM, out_proj_w, out_proj_b, nullptr, out, DM, DM, 0);
}